// round 11
// baseline (speedup 1.0000x reference)
#include <cuda_runtime.h>
#include <cuda_fp16.h>
#include <math.h>
#include <stdint.h>

#define BB   8
#define SRC  512
#define TGT  128
#define DIM  512

// ---------------- scratch (static: allocation-free rule) --------------------
__device__ uint32_t g_dp_h[BB * TGT * 256];   // 1 MB, half2-packed dp
__device__ uint32_t g_mp_h[BB * SRC * 256];   // 4 MB, half2-packed mp
__device__ float    g_e[BB * TGT * SRC];      // 2 MB, masked scores
__device__ float    g_a[BB * TGT * SRC];      // 2 MB, softmax weights

__device__ __forceinline__ uint32_t smem_u32(const void* p) {
    uint32_t a;
    asm("{ .reg .u64 t; cvta.to.shared.u64 t, %1; cvt.u32.u64 %0, t; }"
        : "=r"(a) : "l"(p));
    return a;
}
__device__ __forceinline__ uint32_t cvt_tf32(float f) {
    uint32_t r;
    asm("cvt.rna.tf32.f32 %0, %1;" : "=r"(r) : "f"(f));
    return r;
}
__device__ __forceinline__ void cp_async16(uint32_t dst, const void* src) {
    asm volatile("cp.async.cg.shared.global [%0], [%1], 16;" :: "r"(dst), "l"(src));
}
#define CP_COMMIT()  asm volatile("cp.async.commit_group;" ::: "memory")
#define CP_WAIT(n)   asm volatile("cp.async.wait_group %0;" :: "n"(n) : "memory")

__device__ __forceinline__ void mma_tf32(float* d, uint32_t a0, uint32_t a1,
                                         uint32_t a2, uint32_t a3,
                                         uint32_t b0, uint32_t b1) {
    asm volatile(
        "mma.sync.aligned.m16n8k8.row.col.f32.tf32.tf32.f32 "
        "{%0,%1,%2,%3}, {%4,%5,%6,%7}, {%8,%9}, {%0,%1,%2,%3};"
        : "+f"(d[0]), "+f"(d[1]), "+f"(d[2]), "+f"(d[3])
        : "r"(a0), "r"(a1), "r"(a2), "r"(a3), "r"(b0), "r"(b1));
}
__device__ __forceinline__ uint32_t tanh2(uint32_t x) {
    uint32_t y;
    asm("tanh.approx.f16x2 %0, %1;" : "=r"(y) : "r"(x));
    return y;
}
__device__ __forceinline__ uint32_t pack_h2(float a, float b) {
    __half2 h = __floats2half2_rn(a, b);
    return *reinterpret_cast<uint32_t*>(&h);
}

// ---------------------------------------------------------------------------
// Main GEMM (dp/mp): CTA tile 64x128, KC=32, 3-stage cp.async. grid (4, 80).
// smem: A bufs 3 x (64x36), then B bufs 3 x (32x136).
// ---------------------------------------------------------------------------
#define KC        32
#define AS_STRIDE 36
#define BS_STRIDE 136
#define AS_FLOATS (64 * AS_STRIDE)        // 2304
#define BS_FLOATS (KC * BS_STRIDE)        // 4352
#define GEMM_SMEM_BYTES (3 * (AS_FLOATS + BS_FLOATS) * 4)   // 79872

__device__ __forceinline__ void load_chunk(uint32_t smem_base,
                                           const float* __restrict__ Asrc,
                                           const float* __restrict__ Bsrc,
                                           int M0, int kc0, int buf, int tid)
{
    uint32_t abase = smem_base + (uint32_t)(buf * AS_FLOATS) * 4u;
    #pragma unroll
    for (int j = 0; j < 2; j++) {
        int c = tid + j * 256;
        int row = c >> 3, u = c & 7;
        cp_async16(abase + (uint32_t)(row * AS_STRIDE + u * 4) * 4u,
                   Asrc + (size_t)(M0 + row) * 512 + kc0 + u * 4);
    }
    uint32_t bbase = smem_base + (uint32_t)(3 * AS_FLOATS + buf * BS_FLOATS) * 4u;
    #pragma unroll
    for (int j = 0; j < 4; j++) {
        int c = tid + j * 256;
        int kr = c >> 5, u = c & 31;
        cp_async16(bbase + (uint32_t)(kr * BS_STRIDE + u * 4) * 4u,
                   Bsrc + (size_t)(kc0 + kr) * 512 + u * 4);
    }
}

__global__ __launch_bounds__(256)
void tf32_gemm_kernel(const float* __restrict__ memory,
                      const float* __restrict__ dec,
                      const float* __restrict__ Wa)
{
    extern __shared__ float smf[];
    uint32_t smem_base = smem_u32(smf);

    int tid  = threadIdx.x;
    int wid  = tid >> 5;
    int lane = tid & 31;
    int gid  = lane >> 2;
    int tig  = lane & 3;

    int nb = blockIdx.x;
    int mb = blockIdx.y;
    const float* Asrc;
    uint32_t* Cbase;
    int half, M0;
    if (mb < 16) { half = 0; Asrc = dec;    Cbase = g_dp_h; M0 = mb * 64; }
    else         { half = 1; Asrc = memory; Cbase = g_mp_h; M0 = (mb - 16) * 64; }
    int N0 = nb * 128;
    const float* Wbase = Wa + (size_t)(half * 512) * 512 + N0;

    int wm = (wid & 1) * 32;
    int wn = (wid >> 1) * 32;

    float acc[2][4][4];
    #pragma unroll
    for (int i = 0; i < 2; i++)
        #pragma unroll
        for (int j = 0; j < 4; j++)
            #pragma unroll
            for (int k = 0; k < 4; k++) acc[i][j][k] = 0.f;

    load_chunk(smem_base, Asrc, Wbase, M0, 0, 0, tid);
    CP_COMMIT();
    load_chunk(smem_base, Asrc, Wbase, M0, KC, 1, tid);
    CP_COMMIT();

    for (int ck = 0; ck < 16; ck++) {
        if (ck < 15) { CP_WAIT(1); } else { CP_WAIT(0); }
        __syncthreads();
        if (ck < 14) {
            load_chunk(smem_base, Asrc, Wbase, M0, (ck + 2) * KC, (ck + 2) % 3, tid);
            CP_COMMIT();
        }

        const float* As = smf + (ck % 3) * AS_FLOATS;
        const float* Bs = smf + 3 * AS_FLOATS + (ck % 3) * BS_FLOATS;

        #pragma unroll
        for (int ks = 0; ks < KC; ks += 8) {
            uint32_t b0[4], b1[4];
            #pragma unroll
            for (int na = 0; na < 4; na++) {
                int bn = wn + na * 8 + gid;
                b0[na] = cvt_tf32(Bs[(ks + tig) * BS_STRIDE + bn]);
                b1[na] = cvt_tf32(Bs[(ks + tig + 4) * BS_STRIDE + bn]);
            }
            #pragma unroll
            for (int ma = 0; ma < 2; ma++) {
                int r = wm + ma * 16 + gid;
                uint32_t a0 = cvt_tf32(As[r * AS_STRIDE + ks + tig]);
                uint32_t a1 = cvt_tf32(As[(r + 8) * AS_STRIDE + ks + tig]);
                uint32_t a2 = cvt_tf32(As[r * AS_STRIDE + ks + tig + 4]);
                uint32_t a3 = cvt_tf32(As[(r + 8) * AS_STRIDE + ks + tig + 4]);
                #pragma unroll
                for (int na = 0; na < 4; na++)
                    mma_tf32(acc[ma][na], a0, a1, a2, a3, b0[na], b1[na]);
            }
        }
    }

    // epilogue: pack pairs (c0, c0+1) into half2 words
    #pragma unroll
    for (int ma = 0; ma < 2; ma++) {
        #pragma unroll
        for (int na = 0; na < 4; na++) {
            int r0 = M0 + wm + ma * 16 + gid;
            int c0 = N0 + wn + na * 8 + 2 * tig;   // even
            Cbase[(size_t)r0 * 256 + (c0 >> 1)] =
                pack_h2(acc[ma][na][0], acc[ma][na][1]);
            Cbase[(size_t)(r0 + 8) * 256 + (c0 >> 1)] =
                pack_h2(acc[ma][na][2], acc[ma][na][3]);
        }
    }
}

// ---------------------------------------------------------------------------
// e_kernel: HADD2 + TANH2 + HFMA2, f16 block accumulation (unchanged, at its
// MUFU floor). grid (4 s-tiles, 16 t-tiles, 8 b), 256 thr.
// ---------------------------------------------------------------------------
__global__ __launch_bounds__(256)
void e_kernel(const float* __restrict__ Va,
              const int* __restrict__ mask)
{
    __shared__ uint32_t dp_h[8][256];   // 8 KB

    int b  = blockIdx.z;
    int t0 = blockIdx.y * 8;
    int s0 = blockIdx.x * 128;
    int tid  = threadIdx.x;
    int lane = tid & 31;
    int wid  = tid >> 5;                // 0..7

    for (int i = tid; i < 8 * 256; i += 256)
        dp_h[i >> 8][i & 255] = g_dp_h[(size_t)(b * TGT + t0 + (i >> 8)) * 256 + (i & 255)];

    uint32_t va_h2[8];
    #pragma unroll
    for (int pi = 0; pi < 8; pi++) {
        int p = lane + (pi << 5);
        float2 v = __ldg((const float2*)(Va) + p);
        va_h2[pi] = pack_h2(v.x, v.y);
    }
    __syncthreads();

    const __half2 zero2 = __float2half2_rn(0.f);

    for (int si = wid; si < 128; si += 8) {
        int s = s0 + si;
        const uint32_t* mprow = g_mp_h + (size_t)(b * SRC + s) * 256;
        __half2 acch[8];
        float accf[8];
        #pragma unroll
        for (int t = 0; t < 8; t++) { acch[t] = zero2; accf[t] = 0.f; }

        #pragma unroll
        for (int pi = 0; pi < 8; pi++) {
            int p = lane + (pi << 5);
            uint32_t mu = __ldg(mprow + p);
            __half2 m2 = *reinterpret_cast<__half2*>(&mu);
            __half2 va2 = *reinterpret_cast<__half2*>(&va_h2[pi]);
            #pragma unroll
            for (int t = 0; t < 8; t++) {
                uint32_t du = dp_h[t][p];
                __half2 x = __hadd2(*reinterpret_cast<__half2*>(&du), m2);
                uint32_t yu = tanh2(*reinterpret_cast<uint32_t*>(&x));
                acch[t] = __hfma2(*reinterpret_cast<__half2*>(&yu), va2, acch[t]);
            }
            if (pi == 3 || pi == 7) {
                #pragma unroll
                for (int t = 0; t < 8; t++) {
                    float2 f = __half22float2(acch[t]);
                    accf[t] += f.x + f.y;
                    acch[t] = zero2;
                }
            }
        }
        #pragma unroll
        for (int t = 0; t < 8; t++) {
            #pragma unroll
            for (int off = 16; off > 0; off >>= 1)
                accf[t] += __shfl_xor_sync(0xffffffffu, accf[t], off);
        }
        if (lane == 0) {
            bool mk = mask[b * SRC + s] != 0;
            float* ep = g_e + (size_t)(b * TGT + t0) * SRC + s;
            #pragma unroll
            for (int t = 0; t < 8; t++)
                ep[(size_t)t * SRC] = mk ? accf[t] : -INFINITY;
        }
    }
}

// ---------------------------------------------------------------------------
// softmax: one warp per t-row (1024 rows), writes g_a. grid 128, 256 thr.
// ---------------------------------------------------------------------------
__global__ __launch_bounds__(256)
void softmax_kernel()
{
    int row  = blockIdx.x * 8 + (threadIdx.x >> 5);   // 0..1023
    int lane = threadIdx.x & 31;
    const float* ep = g_e + (size_t)row * SRC;
    float*       ap = g_a + (size_t)row * SRC;

    float v[16];
    float mx = -INFINITY;
    #pragma unroll
    for (int i = 0; i < 4; i++) {
        float4 t = *(const float4*)(ep + lane * 4 + i * 128);
        v[i * 4 + 0] = t.x; v[i * 4 + 1] = t.y;
        v[i * 4 + 2] = t.z; v[i * 4 + 3] = t.w;
        mx = fmaxf(mx, fmaxf(fmaxf(t.x, t.y), fmaxf(t.z, t.w)));
    }
    #pragma unroll
    for (int off = 16; off > 0; off >>= 1)
        mx = fmaxf(mx, __shfl_xor_sync(0xffffffffu, mx, off));
    float sum = 0.f;
    #pragma unroll
    for (int i = 0; i < 16; i++) { v[i] = __expf(v[i] - mx); sum += v[i]; }
    #pragma unroll
    for (int off = 16; off > 0; off >>= 1)
        sum += __shfl_xor_sync(0xffffffffu, sum, off);
    float inv = 1.f / sum;
    #pragma unroll
    for (int i = 0; i < 4; i++) {
        float4 t = make_float4(v[i * 4] * inv, v[i * 4 + 1] * inv,
                               v[i * 4 + 2] * inv, v[i * 4 + 3] * inv);
        *(float4*)(ap + lane * 4 + i * 128) = t;
    }
}

// ---------------------------------------------------------------------------
// ctx tf32 GEMM: out[b] = g_a[b] (128x512) @ memory[b] (512x512).
// CTA tile 32x128, 3-stage. grid (4 n, 4 m, 8 b) = 128 CTAs.
// Warp layout: 8 warps side-by-side in N (16 cols each), warp tile 32x16.
// ---------------------------------------------------------------------------
#define CAS_FLOATS (32 * AS_STRIDE)       // 1152
#define CTX_SMEM_BYTES (3 * (CAS_FLOATS + BS_FLOATS) * 4)   // 66048

__device__ __forceinline__ void ctx_load_chunk(uint32_t smem_base,
                                               const float* __restrict__ Asrc,
                                               const float* __restrict__ Bsrc,
                                               int M0, int kc0, int buf, int tid)
{
    uint32_t abase = smem_base + (uint32_t)(buf * CAS_FLOATS) * 4u;
    {
        int row = tid >> 3, u = tid & 7;    // 32 rows x 8 units
        cp_async16(abase + (uint32_t)(row * AS_STRIDE + u * 4) * 4u,
                   Asrc + (size_t)(M0 + row) * 512 + kc0 + u * 4);
    }
    uint32_t bbase = smem_base + (uint32_t)(3 * CAS_FLOATS + buf * BS_FLOATS) * 4u;
    #pragma unroll
    for (int j = 0; j < 4; j++) {
        int c = tid + j * 256;
        int kr = c >> 5, u = c & 31;
        cp_async16(bbase + (uint32_t)(kr * BS_STRIDE + u * 4) * 4u,
                   Bsrc + (size_t)(kc0 + kr) * 512 + u * 4);
    }
}

__global__ __launch_bounds__(256)
void ctx_gemm_kernel(const float* __restrict__ memory, float* __restrict__ out)
{
    extern __shared__ float smf[];
    uint32_t smem_base = smem_u32(smf);

    int tid  = threadIdx.x;
    int wid  = tid >> 5;
    int lane = tid & 31;
    int gid  = lane >> 2;
    int tig  = lane & 3;

    int nb = blockIdx.x;               // 0..3
    int mb = blockIdx.y;               // 0..3
    int b  = blockIdx.z;
    int M0 = mb * 32;
    int N0 = nb * 128;
    const float* Asrc = g_a + (size_t)b * TGT * SRC;
    const float* Bsrc = memory + (size_t)b * SRC * DIM + N0;
    float* Cb = out + (size_t)b * TGT * DIM;

    int wn = wid * 16;                 // warp n-offset, warp tile 32x16

    float acc[2][2][4];
    #pragma unroll
    for (int i = 0; i < 2; i++)
        #pragma unroll
        for (int j = 0; j < 2; j++)
            #pragma unroll
            for (int k = 0; k < 4; k++) acc[i][j][k] = 0.f;

    ctx_load_chunk(smem_base, Asrc, Bsrc, M0, 0, 0, tid);
    CP_COMMIT();
    ctx_load_chunk(smem_base, Asrc, Bsrc, M0, KC, 1, tid);
    CP_COMMIT();

    for (int ck = 0; ck < 16; ck++) {
        if (ck < 15) { CP_WAIT(1); } else { CP_WAIT(0); }
        __syncthreads();
        if (ck < 14) {
            ctx_load_chunk(smem_base, Asrc, Bsrc, M0, (ck + 2) * KC, (ck + 2) % 3, tid);
            CP_COMMIT();
        }

        const float* As = smf + (ck % 3) * CAS_FLOATS;
        const float* Bs = smf + 3 * CAS_FLOATS + (ck % 3) * BS_FLOATS;

        #pragma unroll
        for (int ks = 0; ks < KC; ks += 8) {
            uint32_t b0[2], b1[2];
            #pragma unroll
            for (int na = 0; na < 2; na++) {
                int bn = wn + na * 8 + gid;
                b0[na] = cvt_tf32(Bs[(ks + tig) * BS_STRIDE + bn]);
                b1[na] = cvt_tf32(Bs[(ks + tig + 4) * BS_STRIDE + bn]);
            }
            #pragma unroll
            for (int ma = 0; ma < 2; ma++) {
                int r = ma * 16 + gid;
                uint32_t a0 = cvt_tf32(As[r * AS_STRIDE + ks + tig]);
                uint32_t a1 = cvt_tf32(As[(r + 8) * AS_STRIDE + ks + tig]);
                uint32_t a2 = cvt_tf32(As[r * AS_STRIDE + ks + tig + 4]);
                uint32_t a3 = cvt_tf32(As[(r + 8) * AS_STRIDE + ks + tig + 4]);
                #pragma unroll
                for (int na = 0; na < 2; na++)
                    mma_tf32(acc[ma][na], a0, a1, a2, a3, b0[na], b1[na]);
            }
        }
    }

    #pragma unroll
    for (int ma = 0; ma < 2; ma++) {
        #pragma unroll
        for (int na = 0; na < 2; na++) {
            int r0 = M0 + ma * 16 + gid;
            int c0 = N0 + wn + na * 8 + 2 * tig;
            float* p0 = Cb + (size_t)r0 * 512 + c0;
            float* p1 = Cb + (size_t)(r0 + 8) * 512 + c0;
            *(float2*)p0 = make_float2(acc[ma][na][0], acc[ma][na][1]);
            *(float2*)p1 = make_float2(acc[ma][na][2], acc[ma][na][3]);
        }
    }
}

// ---------------------------------------------------------------------------
extern "C" void kernel_launch(void* const* d_in, const int* in_sizes, int n_in,
                              void* d_out, int out_size)
{
    const float* memory = (const float*)d_in[0];
    const float* dec    = (const float*)d_in[1];
    const int*   mask   = (const int*)d_in[2];
    const float* Wa     = (const float*)d_in[3];
    const float* Va     = (const float*)d_in[4];
    float* out = (float*)d_out;

    static int configured = 0;
    if (!configured) {
        cudaFuncSetAttribute(tf32_gemm_kernel,
                             cudaFuncAttributeMaxDynamicSharedMemorySize,
                             GEMM_SMEM_BYTES);
        cudaFuncSetAttribute(ctx_gemm_kernel,
                             cudaFuncAttributeMaxDynamicSharedMemorySize,
                             CTX_SMEM_BYTES);
        configured = 1;
    }

    tf32_gemm_kernel<<<dim3(4, 80), 256, GEMM_SMEM_BYTES>>>(memory, dec, Wa);
    e_kernel<<<dim3(4, 16, 8), 256>>>(Va, mask);
    softmax_kernel<<<128, 256>>>();
    ctx_gemm_kernel<<<dim3(4, 4, 8), 256, CTX_SMEM_BYTES>>>(memory, out);
}

// round 13
// speedup vs baseline: 1.0640x; 1.0640x over previous
#include <cuda_runtime.h>
#include <cuda_fp16.h>
#include <math.h>
#include <stdint.h>

#define BB   8
#define SRC  512
#define TGT  128
#define DIM  512

// ---------------- scratch (static: allocation-free rule) --------------------
__device__ uint32_t g_dp_h[BB * TGT * 256];   // 1 MB, half2-packed dp
__device__ uint32_t g_mp_h[BB * SRC * 256];   // 4 MB, half2-packed mp
__device__ float    g_e[BB * TGT * SRC];      // 2 MB, masked scores
__device__ float    g_a[BB * TGT * SRC];      // 2 MB, softmax weights
__device__ int      g_gemm_cnt[BB];
__device__ int      g_e_cnt[BB];
__device__ int      g_sm_cnt[BB];

__device__ __forceinline__ uint32_t smem_u32(const void* p) {
    uint32_t a;
    asm("{ .reg .u64 t; cvta.to.shared.u64 t, %1; cvt.u32.u64 %0, t; }"
        : "=r"(a) : "l"(p));
    return a;
}
__device__ __forceinline__ uint32_t cvt_tf32(float f) {
    uint32_t r;
    asm("cvt.rna.tf32.f32 %0, %1;" : "=r"(r) : "f"(f));
    return r;
}
__device__ __forceinline__ void cp_async16(uint32_t dst, const void* src) {
    asm volatile("cp.async.cg.shared.global [%0], [%1], 16;" :: "r"(dst), "l"(src));
}
#define CP_COMMIT()  asm volatile("cp.async.commit_group;" ::: "memory")
#define CP_WAIT(n)   asm volatile("cp.async.wait_group %0;" :: "n"(n) : "memory")

__device__ __forceinline__ void mma_tf32(float* d, uint32_t a0, uint32_t a1,
                                         uint32_t a2, uint32_t a3,
                                         uint32_t b0, uint32_t b1) {
    asm volatile(
        "mma.sync.aligned.m16n8k8.row.col.f32.tf32.tf32.f32 "
        "{%0,%1,%2,%3}, {%4,%5,%6,%7}, {%8,%9}, {%0,%1,%2,%3};"
        : "+f"(d[0]), "+f"(d[1]), "+f"(d[2]), "+f"(d[3])
        : "r"(a0), "r"(a1), "r"(a2), "r"(a3), "r"(b0), "r"(b1));
}
__device__ __forceinline__ uint32_t tanh2(uint32_t x) {
    uint32_t y;
    asm("tanh.approx.f16x2 %0, %1;" : "=r"(y) : "r"(x));
    return y;
}
__device__ __forceinline__ uint32_t pack_h2(float a, float b) {
    __half2 h = __floats2half2_rn(a, b);
    return *reinterpret_cast<uint32_t*>(&h);
}

// ---------------- sync helpers ----------------------------------------------
__device__ __forceinline__ void wait_count(int* cnt, int target) {
    if (threadIdx.x == 0) {
        while (atomicAdd(cnt, 0) < target) __nanosleep(128);
        __threadfence();
    }
    __syncthreads();
}
__device__ __forceinline__ void signal_count(int* cnt) {
    __syncthreads();
    if (threadIdx.x == 0) { __threadfence(); atomicAdd(cnt, 1); }
}

// ---------------- tiling constants ------------------------------------------
#define KC        32
#define AS_STRIDE 36
#define BS_STRIDE 136
#define AS_FLOATS (64 * AS_STRIDE)        // 2304
#define BS_FLOATS (KC * BS_STRIDE)        // 4352
#define CAS_FLOATS (32 * AS_STRIDE)       // 1152
#define MEGA_SMEM_BYTES (2 * (AS_FLOATS + BS_FLOATS) * 4)   // 53248

// grid layout
#define GEMM_CTAS_PER_B 40
#define E_CTAS_PER_B    64
#define SM_CTAS_PER_B   16
#define CTX_CTAS_PER_B  16
#define GEMM_BASE  0
#define E_BASE     (GEMM_CTAS_PER_B * BB)                 // 320
#define SM_BASE    (E_BASE + E_CTAS_PER_B * BB)           // 832
#define CTX_BASE   (SM_BASE + SM_CTAS_PER_B * BB)         // 960
#define TOTAL_CTAS (CTX_BASE + CTX_CTAS_PER_B * BB)       // 1088

// ---------------------------------------------------------------------------
__global__ void reset_kernel()
{
    int i = threadIdx.x;
    if (i < BB) { g_gemm_cnt[i] = 0; g_e_cnt[i] = 0; g_sm_cnt[i] = 0; }
}

// ---------------------------------------------------------------------------
__device__ __forceinline__ void load_chunk(uint32_t smem_base,
                                           const float* __restrict__ Asrc,
                                           const float* __restrict__ Bsrc,
                                           int M0, int kc0, int buf, int tid)
{
    uint32_t abase = smem_base + (uint32_t)(buf * AS_FLOATS) * 4u;
    #pragma unroll
    for (int j = 0; j < 2; j++) {
        int c = tid + j * 256;
        int row = c >> 3, u = c & 7;
        cp_async16(abase + (uint32_t)(row * AS_STRIDE + u * 4) * 4u,
                   Asrc + (size_t)(M0 + row) * 512 + kc0 + u * 4);
    }
    uint32_t bbase = smem_base + (uint32_t)(2 * AS_FLOATS + buf * BS_FLOATS) * 4u;
    #pragma unroll
    for (int j = 0; j < 4; j++) {
        int c = tid + j * 256;
        int kr = c >> 5, u = c & 31;
        cp_async16(bbase + (uint32_t)(kr * BS_STRIDE + u * 4) * 4u,
                   Bsrc + (size_t)(kc0 + kr) * 512 + u * 4);
    }
}

__device__ void gemm_phase(float* smf, const float* __restrict__ memory,
                           const float* __restrict__ dec,
                           const float* __restrict__ Wa, int bid)
{
    uint32_t smem_base = smem_u32(smf);
    int tid  = threadIdx.x;
    int wid  = tid >> 5;
    int lane = tid & 31;
    int gid  = lane >> 2;
    int tig  = lane & 3;

    int b     = bid / GEMM_CTAS_PER_B;
    int inner = bid % GEMM_CTAS_PER_B;
    int nb = inner & 3;
    int mb = inner >> 2;               // 0..9
    const float* Asrc;
    uint32_t* Cbase;
    int half, M0;
    if (mb < 2) { half = 0; Asrc = dec;    Cbase = g_dp_h; M0 = b * TGT + mb * 64; }
    else        { half = 1; Asrc = memory; Cbase = g_mp_h; M0 = b * SRC + (mb - 2) * 64; }
    int N0 = nb * 128;
    const float* Wbase = Wa + (size_t)(half * 512) * 512 + N0;

    int wm = (wid & 1) * 32;
    int wn = (wid >> 1) * 32;

    float acc[2][4][4];
    #pragma unroll
    for (int i = 0; i < 2; i++)
        #pragma unroll
        for (int j = 0; j < 4; j++)
            #pragma unroll
            for (int k = 0; k < 4; k++) acc[i][j][k] = 0.f;

    load_chunk(smem_base, Asrc, Wbase, M0, 0, 0, tid);
    CP_COMMIT();

    int buf = 0;
    for (int ck = 0; ck < 16; ck++) {
        if (ck < 15) {
            load_chunk(smem_base, Asrc, Wbase, M0, (ck + 1) * KC, buf ^ 1, tid);
            CP_COMMIT();
            CP_WAIT(1);
        } else {
            CP_WAIT(0);
        }
        __syncthreads();

        const float* As = smf + buf * AS_FLOATS;
        const float* Bs = smf + 2 * AS_FLOATS + buf * BS_FLOATS;

        #pragma unroll
        for (int ks = 0; ks < KC; ks += 8) {
            uint32_t b0[4], b1[4];
            #pragma unroll
            for (int na = 0; na < 4; na++) {
                int bn = wn + na * 8 + gid;
                b0[na] = cvt_tf32(Bs[(ks + tig) * BS_STRIDE + bn]);
                b1[na] = cvt_tf32(Bs[(ks + tig + 4) * BS_STRIDE + bn]);
            }
            #pragma unroll
            for (int ma = 0; ma < 2; ma++) {
                int r = wm + ma * 16 + gid;
                uint32_t a0 = cvt_tf32(As[r * AS_STRIDE + ks + tig]);
                uint32_t a1 = cvt_tf32(As[(r + 8) * AS_STRIDE + ks + tig]);
                uint32_t a2 = cvt_tf32(As[r * AS_STRIDE + ks + tig + 4]);
                uint32_t a3 = cvt_tf32(As[(r + 8) * AS_STRIDE + ks + tig + 4]);
                #pragma unroll
                for (int na = 0; na < 4; na++)
                    mma_tf32(acc[ma][na], a0, a1, a2, a3, b0[na], b1[na]);
            }
        }
        __syncthreads();
        buf ^= 1;
    }

    #pragma unroll
    for (int ma = 0; ma < 2; ma++) {
        #pragma unroll
        for (int na = 0; na < 4; na++) {
            int r0 = M0 + wm + ma * 16 + gid;
            int c0 = N0 + wn + na * 8 + 2 * tig;
            Cbase[(size_t)r0 * 256 + (c0 >> 1)] =
                pack_h2(acc[ma][na][0], acc[ma][na][1]);
            Cbase[(size_t)(r0 + 8) * 256 + (c0 >> 1)] =
                pack_h2(acc[ma][na][2], acc[ma][na][3]);
        }
    }
    signal_count(&g_gemm_cnt[b]);
}

// ---------------------------------------------------------------------------
__device__ void e_phase(float* smf, const float* __restrict__ Va,
                        const int* __restrict__ mask, int bid)
{
    uint32_t* dp_h = (uint32_t*)smf;    // [8][256] in dynamic smem

    int b     = bid / E_CTAS_PER_B;
    int inner = bid % E_CTAS_PER_B;
    int s0 = (inner & 3) * 128;
    int t0 = (inner >> 2) * 8;
    int tid  = threadIdx.x;
    int lane = tid & 31;
    int wid  = tid >> 5;

    wait_count(&g_gemm_cnt[b], GEMM_CTAS_PER_B);

    for (int i = tid; i < 8 * 256; i += 256)
        dp_h[i] = g_dp_h[(size_t)(b * TGT + t0 + (i >> 8)) * 256 + (i & 255)];

    uint32_t va_h2[8];
    #pragma unroll
    for (int pi = 0; pi < 8; pi++) {
        int p = lane + (pi << 5);
        float2 v = __ldg((const float2*)(Va) + p);
        va_h2[pi] = pack_h2(v.x, v.y);
    }
    __syncthreads();

    const __half2 zero2 = __float2half2_rn(0.f);

    for (int si = wid; si < 128; si += 8) {
        int s = s0 + si;
        const uint32_t* mprow = g_mp_h + (size_t)(b * SRC + s) * 256;
        __half2 acch[8];
        float accf[8];
        #pragma unroll
        for (int t = 0; t < 8; t++) { acch[t] = zero2; accf[t] = 0.f; }

        #pragma unroll
        for (int pi = 0; pi < 8; pi++) {
            int p = lane + (pi << 5);
            uint32_t mu = __ldg(mprow + p);
            __half2 m2 = *reinterpret_cast<__half2*>(&mu);
            __half2 va2 = *reinterpret_cast<__half2*>(&va_h2[pi]);
            #pragma unroll
            for (int t = 0; t < 8; t++) {
                uint32_t du = dp_h[t * 256 + p];
                __half2 x = __hadd2(*reinterpret_cast<__half2*>(&du), m2);
                uint32_t yu = tanh2(*reinterpret_cast<uint32_t*>(&x));
                acch[t] = __hfma2(*reinterpret_cast<__half2*>(&yu), va2, acch[t]);
            }
            if (pi == 3 || pi == 7) {
                #pragma unroll
                for (int t = 0; t < 8; t++) {
                    float2 f = __half22float2(acch[t]);
                    accf[t] += f.x + f.y;
                    acch[t] = zero2;
                }
            }
        }
        #pragma unroll
        for (int t = 0; t < 8; t++) {
            #pragma unroll
            for (int off = 16; off > 0; off >>= 1)
                accf[t] += __shfl_xor_sync(0xffffffffu, accf[t], off);
        }
        if (lane == 0) {
            bool mk = mask[b * SRC + s] != 0;
            float* ep = g_e + (size_t)(b * TGT + t0) * SRC + s;
            #pragma unroll
            for (int t = 0; t < 8; t++)
                ep[(size_t)t * SRC] = mk ? accf[t] : -INFINITY;
        }
    }
    signal_count(&g_e_cnt[b]);
}

// ---------------------------------------------------------------------------
__device__ void softmax_phase(int bid)
{
    int b     = bid / SM_CTAS_PER_B;
    int inner = bid % SM_CTAS_PER_B;

    wait_count(&g_e_cnt[b], E_CTAS_PER_B);

    int row  = b * TGT + inner * 8 + (threadIdx.x >> 5);
    int lane = threadIdx.x & 31;
    const float* ep = g_e + (size_t)row * SRC;
    float*       ap = g_a + (size_t)row * SRC;

    float v[16];
    float mx = -INFINITY;
    #pragma unroll
    for (int i = 0; i < 4; i++) {
        float4 t = *(const float4*)(ep + lane * 4 + i * 128);
        v[i * 4 + 0] = t.x; v[i * 4 + 1] = t.y;
        v[i * 4 + 2] = t.z; v[i * 4 + 3] = t.w;
        mx = fmaxf(mx, fmaxf(fmaxf(t.x, t.y), fmaxf(t.z, t.w)));
    }
    #pragma unroll
    for (int off = 16; off > 0; off >>= 1)
        mx = fmaxf(mx, __shfl_xor_sync(0xffffffffu, mx, off));
    float sum = 0.f;
    #pragma unroll
    for (int i = 0; i < 16; i++) { v[i] = __expf(v[i] - mx); sum += v[i]; }
    #pragma unroll
    for (int off = 16; off > 0; off >>= 1)
        sum += __shfl_xor_sync(0xffffffffu, sum, off);
    float inv = 1.f / sum;
    #pragma unroll
    for (int i = 0; i < 4; i++) {
        float4 t = make_float4(v[i * 4] * inv, v[i * 4 + 1] * inv,
                               v[i * 4 + 2] * inv, v[i * 4 + 3] * inv);
        *(float4*)(ap + lane * 4 + i * 128) = t;
    }
    signal_count(&g_sm_cnt[b]);
}

// ---------------------------------------------------------------------------
__device__ __forceinline__ void ctx_load_chunk(uint32_t smem_base,
                                               const float* __restrict__ Asrc,
                                               const float* __restrict__ Bsrc,
                                               int M0, int kc0, int buf, int tid)
{
    uint32_t abase = smem_base + (uint32_t)(buf * CAS_FLOATS) * 4u;
    {
        int row = tid >> 3, u = tid & 7;
        cp_async16(abase + (uint32_t)(row * AS_STRIDE + u * 4) * 4u,
                   Asrc + (size_t)(M0 + row) * 512 + kc0 + u * 4);
    }
    uint32_t bbase = smem_base + (uint32_t)(2 * CAS_FLOATS + buf * BS_FLOATS) * 4u;
    #pragma unroll
    for (int j = 0; j < 4; j++) {
        int c = tid + j * 256;
        int kr = c >> 5, u = c & 31;
        cp_async16(bbase + (uint32_t)(kr * BS_STRIDE + u * 4) * 4u,
                   Bsrc + (size_t)(kc0 + kr) * 512 + u * 4);
    }
}

__device__ void ctx_phase(float* smf, const float* __restrict__ memory,
                          float* __restrict__ out, int bid)
{
    uint32_t smem_base = smem_u32(smf);
    int tid  = threadIdx.x;
    int wid  = tid >> 5;
    int lane = tid & 31;
    int gid  = lane >> 2;
    int tig  = lane & 3;

    int b     = bid / CTX_CTAS_PER_B;
    int inner = bid % CTX_CTAS_PER_B;
    int nb = inner & 3;
    int mb = inner >> 2;
    int M0 = mb * 32;
    int N0 = nb * 128;
    const float* Asrc = g_a + (size_t)b * TGT * SRC;
    const float* Bsrc = memory + (size_t)b * SRC * DIM + N0;
    float* Cb = out + (size_t)b * TGT * DIM;

    wait_count(&g_sm_cnt[b], SM_CTAS_PER_B);

    int wn = wid * 16;

    float acc[2][2][4];
    #pragma unroll
    for (int i = 0; i < 2; i++)
        #pragma unroll
        for (int j = 0; j < 2; j++)
            #pragma unroll
            for (int k = 0; k < 4; k++) acc[i][j][k] = 0.f;

    ctx_load_chunk(smem_base, Asrc, Bsrc, M0, 0, 0, tid);
    CP_COMMIT();

    int buf = 0;
    for (int ck = 0; ck < 16; ck++) {
        if (ck < 15) {
            ctx_load_chunk(smem_base, Asrc, Bsrc, M0, (ck + 1) * KC, buf ^ 1, tid);
            CP_COMMIT();
            CP_WAIT(1);
        } else {
            CP_WAIT(0);
        }
        __syncthreads();

        const float* As = smf + buf * CAS_FLOATS;
        const float* Bs = smf + 2 * CAS_FLOATS + buf * BS_FLOATS;

        #pragma unroll
        for (int ks = 0; ks < KC; ks += 8) {
            uint32_t b0[2], b1[2];
            #pragma unroll
            for (int na = 0; na < 2; na++) {
                int bn = wn + na * 8 + gid;
                b0[na] = cvt_tf32(Bs[(ks + tig) * BS_STRIDE + bn]);
                b1[na] = cvt_tf32(Bs[(ks + tig + 4) * BS_STRIDE + bn]);
            }
            #pragma unroll
            for (int ma = 0; ma < 2; ma++) {
                int r = ma * 16 + gid;
                uint32_t a0 = cvt_tf32(As[r * AS_STRIDE + ks + tig]);
                uint32_t a1 = cvt_tf32(As[(r + 8) * AS_STRIDE + ks + tig]);
                uint32_t a2 = cvt_tf32(As[r * AS_STRIDE + ks + tig + 4]);
                uint32_t a3 = cvt_tf32(As[(r + 8) * AS_STRIDE + ks + tig + 4]);
                #pragma unroll
                for (int na = 0; na < 2; na++)
                    mma_tf32(acc[ma][na], a0, a1, a2, a3, b0[na], b1[na]);
            }
        }
        __syncthreads();
        buf ^= 1;
    }

    #pragma unroll
    for (int ma = 0; ma < 2; ma++) {
        #pragma unroll
        for (int na = 0; na < 2; na++) {
            int r0 = M0 + ma * 16 + gid;
            int c0 = N0 + wn + na * 8 + 2 * tig;
            float* p0 = Cb + (size_t)r0 * 512 + c0;
            float* p1 = Cb + (size_t)(r0 + 8) * 512 + c0;
            *(float2*)p0 = make_float2(acc[ma][na][0], acc[ma][na][1]);
            *(float2*)p1 = make_float2(acc[ma][na][2], acc[ma][na][3]);
        }
    }
}

// ---------------------------------------------------------------------------
__global__ __launch_bounds__(256)
void mega_kernel(const float* __restrict__ memory,
                 const float* __restrict__ dec,
                 const float* __restrict__ Wa,
                 const float* __restrict__ Va,
                 const int* __restrict__ mask,
                 float* __restrict__ out)
{
    extern __shared__ float smf[];
    int bid = blockIdx.x;

    if (bid < E_BASE) {
        gemm_phase(smf, memory, dec, Wa, bid - GEMM_BASE);
    } else if (bid < SM_BASE) {
        e_phase(smf, Va, mask, bid - E_BASE);
    } else if (bid < CTX_BASE) {
        softmax_phase(bid - SM_BASE);
    } else {
        ctx_phase(smf, memory, out, bid - CTX_BASE);
    }
}

// ---------------------------------------------------------------------------
extern "C" void kernel_launch(void* const* d_in, const int* in_sizes, int n_in,
                              void* d_out, int out_size)
{
    const float* memory = (const float*)d_in[0];
    const float* dec    = (const float*)d_in[1];
    const int*   mask   = (const int*)d_in[2];
    const float* Wa     = (const float*)d_in[3];
    const float* Va     = (const float*)d_in[4];
    float* out = (float*)d_out;

    static int configured = 0;
    if (!configured) {
        cudaFuncSetAttribute(mega_kernel,
                             cudaFuncAttributeMaxDynamicSharedMemorySize,
                             MEGA_SMEM_BYTES);
        configured = 1;
    }

    reset_kernel<<<1, 32>>>();
    mega_kernel<<<TOTAL_CTAS, 256, MEGA_SMEM_BYTES>>>(
        memory, dec, Wa, Va, mask, out);
}